// round 17
// baseline (speedup 1.0000x reference)
#include <cuda_runtime.h>
#include <cuda_fp16.h>
#include <math.h>
#include <stdint.h>

// Fused flash-style self-attention, sm_103-safe warp MMA.
// R17: QK via int8 IMMA (m16n8k32) with PER-ROW amax scaling (no clamping):
//   x_row = (256a + c) * r_row, r = amax/32512. 3 exact integer passes, s = U * r_i * r_j.
// PV fp16 1-term. Key compaction. exp via MUFU ex2. Lazy-offset softmax. cp.async tiles.

namespace {

constexpr int B_ = 8;
constexpr int L_ = 2048;
constexpr int D_ = 256;
constexpr int BM = 128;
constexpr int BN = 64;
constexpr int NT = 256;          // 8 warps
constexpr int NTILES = L_ / BN;  // 32 max

// smem byte offsets
constexpr int QA_S  = 0;         // 128 x 256B int8 limb a
constexpr int QB_S  = 32768;     // limb b
constexpr int KA_S  = 65536;     // 2 x 16384 (dbl)
constexpr int KB_S  = 98304;     // 16384 (single)
constexpr int VH_S  = 114688;    // 2 x 32768 fp16 hi (dbl)
constexpr int GIDX  = 180224;    // 2 x 128 (slot->row shorts)
constexpr int RKS   = 180480;    // 2 x 256 (slot r floats)
constexpr int SMEM_TOTAL = 180992;

constexpr float L2E = 1.4426950408889634f;

// gmem images
__device__ unsigned char g_qa[B_ * L_ * 256];             // int8 limb a, swizzled rows
__device__ unsigned char g_qb[B_ * L_ * 256];
__device__ unsigned char g_ka[B_ * NTILES * 16384];       // compacted key limb a tiles
__device__ unsigned char g_kb[B_ * NTILES * 16384];
__device__ unsigned char g_vh[B_ * NTILES * 32768];       // compacted fp16-hi V tiles
__device__ __align__(16) short g_kidx[B_ * L_];           // slot -> row (-1 pad)
__device__ short g_slot[B_ * L_];                         // row -> slot (-1 masked)
__device__ __align__(16) float g_r[B_ * L_];              // per-row r = amax/32512
__device__ __align__(16) float g_rk[B_ * L_];             // per-slot r (compacted)
__device__ int g_ntiles[B_];

// ---------------- helpers ----------------

__device__ __forceinline__ uint32_t smem_u32(const void* p) {
  uint32_t a;
  asm("{ .reg .u64 t; cvta.to.shared.u64 t, %1; cvt.u32.u64 %0, t; }" : "=r"(a) : "l"(p));
  return a;
}

// int8 row (256B): swizzled offset, ch = 16B chunk index 0..15
__device__ __forceinline__ uint32_t swI(int row, int ch) {
  return (uint32_t)(row * 256) + (uint32_t)(((ch ^ (row & 7)) & 15) << 4);
}
// fp16 row (512B): d = fp16 elem index multiple of 8
__device__ __forceinline__ uint32_t swH(int row, int d) {
  return (uint32_t)(row * 512) + ((((uint32_t)(d >> 3) ^ (uint32_t)(row & 7)) & 31u) * 16u);
}

__device__ __forceinline__ void ldsm4(uint32_t (&r)[4], uint32_t addr) {
  asm volatile("ldmatrix.sync.aligned.m8n8.x4.shared.b16 {%0,%1,%2,%3}, [%4];"
               : "=r"(r[0]), "=r"(r[1]), "=r"(r[2]), "=r"(r[3]) : "r"(addr));
}
__device__ __forceinline__ void ldsm4t(uint32_t (&r)[4], uint32_t addr) {
  asm volatile("ldmatrix.sync.aligned.m8n8.x4.trans.shared.b16 {%0,%1,%2,%3}, [%4];"
               : "=r"(r[0]), "=r"(r[1]), "=r"(r[2]), "=r"(r[3]) : "r"(addr));
}

__device__ __forceinline__ void mmaf16(float (&d)[4], const uint32_t (&a)[4],
                                       uint32_t b0, uint32_t b1) {
  asm volatile(
    "mma.sync.aligned.m16n8k16.row.col.f32.f16.f16.f32 "
    "{%0,%1,%2,%3}, {%4,%5,%6,%7}, {%8,%9}, {%0,%1,%2,%3};"
    : "+f"(d[0]), "+f"(d[1]), "+f"(d[2]), "+f"(d[3])
    : "r"(a[0]), "r"(a[1]), "r"(a[2]), "r"(a[3]), "r"(b0), "r"(b1));
}

__device__ __forceinline__ void mmai8(int (&d)[4], const uint32_t (&a)[4],
                                      uint32_t b0, uint32_t b1) {
  asm volatile(
    "mma.sync.aligned.m16n8k32.row.col.s32.s8.s8.s32 "
    "{%0,%1,%2,%3}, {%4,%5,%6,%7}, {%8,%9}, {%0,%1,%2,%3};"
    : "+r"(d[0]), "+r"(d[1]), "+r"(d[2]), "+r"(d[3])
    : "r"(a[0]), "r"(a[1]), "r"(a[2]), "r"(a[3]), "r"(b0), "r"(b1));
}

__device__ __forceinline__ uint32_t packh2(float a, float b) {
  __half2 h = __floats2half2_rn(a, b);
  return *reinterpret_cast<uint32_t*>(&h);
}

__device__ __forceinline__ float ex2f(float t) {
  float r;
  asm("ex2.approx.f32 %0, %1;" : "=f"(r) : "f"(t));
  return r;
}

__device__ __forceinline__ void cpa16(uint32_t dst, const void* src) {
  asm volatile("cp.async.cg.shared.global [%0], [%1], 16;" :: "r"(dst), "l"(src));
}
#define CP_COMMIT() asm volatile("cp.async.commit_group;" ::: "memory")
#define CP_WAIT0()  asm volatile("cp.async.wait_group 0;" ::: "memory")

__device__ __forceinline__ void issue16k(uint32_t dst, const unsigned char* src, int tid) {
  #pragma unroll
  for (int j = 0; j < 4; j++) cpa16(dst + tid * 64 + j * 16, src + tid * 64 + j * 16);
}
__device__ __forceinline__ void issue32k(uint32_t dst, const unsigned char* src, int tid) {
  #pragma unroll
  for (int j = 0; j < 8; j++) cpa16(dst + tid * 128 + j * 16, src + tid * 128 + j * 16);
}

// ---- amax: per-row max|x|, r = amax/32512 (one warp per row) ----
__global__ void amax_kernel(const float* __restrict__ x)
{
  const int warp = (blockIdx.x * blockDim.x + threadIdx.x) >> 5;   // B*L warps
  const int lane = threadIdx.x & 31;
  const float* src = x + (size_t)warp * D_;
  float mx = 0.f;
  #pragma unroll
  for (int i = 0; i < 8; i++) mx = fmaxf(mx, fabsf(src[i * 32 + lane]));
  #pragma unroll
  for (int o = 16; o >= 1; o >>= 1)
    mx = fmaxf(mx, __shfl_xor_sync(0xffffffffu, mx, o));
  if (lane == 0) g_r[warp] = fmaxf(mx, 1e-6f) * (1.f / 32512.f);
}

// ---- scan: mask dtype detect + compaction (fwd+inv maps) ----
__global__ void scan_mask_kernel(const void* __restrict__ xmask)
{
  const int b   = blockIdx.x;
  const int tid = threadIdx.x;

  const unsigned int* mw = (const unsigned int*)xmask;
  int not32 = 0, notbyte = 0;
  for (int i = tid; i < 2048; i += 256) {
    unsigned int w = mw[i];
    if (w > 1u) not32 = 1;
    #pragma unroll
    for (int k = 0; k < 4; k++)
      if (((w >> (8 * k)) & 0xFFu) > 1u) notbyte = 1;
  }
  __shared__ int s32, sbyte;
  if (tid == 0) { s32 = 0; sbyte = 0; }
  __syncthreads();
  if (not32)   atomicOr(&s32, 1);
  if (notbyte) atomicOr(&sbyte, 1);
  __syncthreads();
  const int mtype = (!s32) ? 0 : (!sbyte ? 1 : 2);

  int flags[8], cnt = 0;
  #pragma unroll
  for (int k = 0; k < 8; k++) {
    const int i = tid * 8 + k;
    const size_t gi = (size_t)b * L_ + i;
    int masked;
    if (mtype == 0)      masked = ((const int*)xmask)[gi] != 0;
    else if (mtype == 1) masked = ((const unsigned char*)xmask)[gi] != 0;
    else                 masked = ((const float*)xmask)[gi] != 0.f;
    flags[k] = !masked;
    cnt += flags[k];
  }

  const int lane = tid & 31, wid = tid >> 5;
  int pre = cnt;
  #pragma unroll
  for (int o = 1; o < 32; o <<= 1) {
    int v = __shfl_up_sync(0xffffffffu, pre, o);
    if (lane >= o) pre += v;
  }
  const int excl = pre - cnt;
  __shared__ int wsum[8];
  if (lane == 31) wsum[wid] = pre;
  __syncthreads();
  int wbase = 0;
  for (int k = 0; k < wid; k++) wbase += wsum[k];

  int r = wbase + excl;
  #pragma unroll
  for (int k = 0; k < 8; k++) {
    const int row = tid * 8 + k;
    if (flags[k]) {
      g_kidx[b * L_ + r] = (short)row;
      g_slot[b * L_ + row] = (short)r;
      r++;
    } else {
      g_slot[b * L_ + row] = -1;
    }
  }

  __shared__ int total_s;
  if (tid == 255) total_s = wbase + pre;
  __syncthreads();
  const int n = total_s;
  const int npad = (n + 63) & ~63;
  for (int s = n + tid; s < npad; s += 256) g_kidx[b * L_ + s] = -1;
  if (tid == 0) g_ntiles[b] = npad >> 6;
}

// ---- prep: per-row-scaled int8 limbs for Q + gathered K limbs + V fp16-hi ----
__global__ void prep_kernel(const float* __restrict__ x)
{
  const int idx = blockIdx.x * blockDim.x + threadIdx.x;  // B*2048*16
  const int d16 = idx & 15;                  // 16-elem chunk within row
  const int row = (idx >> 4) & (L_ - 1);
  const int b   = idx >> 15;

  const float rrow = g_r[b * L_ + row];
  const float iq = 1.f / rrow;               // = 32512/amax

  const float* src = x + ((size_t)(b * L_ + row)) * D_ + d16 * 16;
  float v[16];
  #pragma unroll
  for (int j = 0; j < 16; j += 4) {
    float4 t = *reinterpret_cast<const float4*>(src + j);
    v[j] = t.x; v[j+1] = t.y; v[j+2] = t.z; v[j+3] = t.w;
  }

  // int8 limbs: x = (a*256 + c) * rrow
  uint32_t pa[4], pc[4];
  #pragma unroll
  for (int g = 0; g < 4; g++) {
    uint32_t wa = 0, wc = 0;
    #pragma unroll
    for (int j = 0; j < 4; j++) {
      int X = __float2int_rn(v[4*g+j] * iq);
      X = max(-32512, min(32512, X));
      int a = (X + 128) >> 8;
      int c = X - (a << 8);
      wa |= ((uint32_t)(a & 255)) << (8 * j);
      wc |= ((uint32_t)(c & 255)) << (8 * j);
    }
    pa[g] = wa; pc[g] = wc;
  }
  // fp16 hi
  uint32_t ph[8];
  #pragma unroll
  for (int j = 0; j < 8; j++) ph[j] = packh2(v[2*j], v[2*j+1]);

  // Q images (row-relative swizzle)
  {
    const uint32_t base = (uint32_t)((b * L_ + row) << 8);
    const uint32_t off = base + (uint32_t)(((d16 ^ (row & 7)) & 15) << 4);
    *reinterpret_cast<uint4*>(g_qa + off) = make_uint4(pa[0], pa[1], pa[2], pa[3]);
    *reinterpret_cast<uint4*>(g_qb + off) = make_uint4(pc[0], pc[1], pc[2], pc[3]);
  }

  // compacted K / V images
  const int slot = g_slot[b * L_ + row];
  if (slot >= 0) {
    const int tile = slot >> 6;
    const int sr = slot & 63;
    const uint32_t kbase = ((uint32_t)(b * NTILES + tile) << 14);
    const uint32_t koff = kbase + swI(sr, d16);
    *reinterpret_cast<uint4*>(g_ka + koff) = make_uint4(pa[0], pa[1], pa[2], pa[3]);
    *reinterpret_cast<uint4*>(g_kb + koff) = make_uint4(pc[0], pc[1], pc[2], pc[3]);
    const uint32_t vbase = ((uint32_t)(b * NTILES + tile) << 15);
    *reinterpret_cast<uint4*>(g_vh + vbase + swH(sr, d16 * 16))     = make_uint4(ph[0], ph[1], ph[2], ph[3]);
    *reinterpret_cast<uint4*>(g_vh + vbase + swH(sr, d16 * 16 + 8)) = make_uint4(ph[4], ph[5], ph[6], ph[7]);
    if (d16 == 0) g_rk[b * L_ + slot] = rrow;
  }
}

// zero-fill padding slots of the last tile of each batch
__global__ void pad_k_kernel()
{
  const int idx = blockIdx.x * blockDim.x + threadIdx.x;  // B*64*16
  const int d16 = idx & 15;
  const int sr64 = (idx >> 4) & 63;
  const int b = idx >> 10;
  const int ntiles = g_ntiles[b];
  const int slot = (ntiles - 1) * 64 + sr64;
  if (g_kidx[b * L_ + slot] >= 0) return;
  const int tile = slot >> 6;
  const int sr = slot & 63;
  const uint32_t kbase = ((uint32_t)(b * NTILES + tile) << 14);
  const uint32_t koff = kbase + swI(sr, d16);
  *reinterpret_cast<uint4*>(g_ka + koff) = make_uint4(0, 0, 0, 0);
  *reinterpret_cast<uint4*>(g_kb + koff) = make_uint4(0, 0, 0, 0);
  const uint32_t vbase = ((uint32_t)(b * NTILES + tile) << 15);
  *reinterpret_cast<uint4*>(g_vh + vbase + swH(sr, d16 * 16)) = make_uint4(0, 0, 0, 0);
  *reinterpret_cast<uint4*>(g_vh + vbase + swH(sr, d16 * 16 + 8)) = make_uint4(0, 0, 0, 0);
  if (d16 == 0) g_rk[b * L_ + slot] = 0.f;
}

// ---------------- main kernel ----------------

__global__ void __launch_bounds__(NT, 1)
attn_kernel(float* __restrict__ out)
{
  extern __shared__ char sm[];
  const uint32_t smb = smem_u32(sm);

  const int b    = blockIdx.y;
  const int q0   = blockIdx.x * BM;
  const int tid  = threadIdx.x;
  const int w    = tid >> 5;
  const int lane = tid & 31;
  const int ntiles = g_ntiles[b];

  // ---- prologue ----
  {
    issue32k(smb + QA_S, g_qa + ((size_t)(b * L_ + q0) << 8), tid);
    issue32k(smb + QB_S, g_qb + ((size_t)(b * L_ + q0) << 8), tid);
    issue16k(smb + KA_S, g_ka + ((size_t)(b * NTILES) << 14), tid);
    issue16k(smb + KB_S, g_kb + ((size_t)(b * NTILES) << 14), tid);
    issue32k(smb + VH_S, g_vh + ((size_t)(b * NTILES) << 15), tid);
    if (tid < 8)
      cpa16(smb + GIDX + tid * 16,
            (const unsigned char*)g_kidx + (size_t)b * L_ * 2 + tid * 16);
    if (tid < 16)
      cpa16(smb + RKS + tid * 16,
            (const unsigned char*)g_rk + (size_t)b * L_ * 4 + tid * 16);
    CP_COMMIT();
    CP_WAIT0();
  }
  __syncthreads();

  // lane decomposition
  const int g  = lane >> 2;
  const int t4 = lane & 3;
  const int m  = lane >> 3;
  const int i8 = lane & 7;

  const int rowQ = 16 * w + (m & 1) * 8 + i8;     // Q row 0..127 for A frags
  const int chA  = (m >> 1);                      // A k-16B-half selector
  const int keyB = (m >> 1) * 8 + i8;             // key row base for B frags
  const int chB  = (m & 1);                       // B k-16B-half selector
  const int keyV = (m & 1) * 8 + i8;              // V row for PV (trans)
  const int dVoff = (m >> 1) * 8;

  const int qa = q0 + 16 * w + g;
  const int qb = qa + 8;
  const float rq0 = g_r[b * L_ + qa];
  const float rq1 = g_r[b * L_ + qb];

  float o[32][4];
  #pragma unroll
  for (int n = 0; n < 32; n++)
    #pragma unroll
    for (int c = 0; c < 4; c++) o[n][c] = 0.f;
  float rs0 = 0.f, rs1 = 0.f;
  float off0 = 0.f, off1 = 0.f;
  float c0 = 0.f, c1 = 0.f;

  for (int t = 0; t < ntiles; ++t) {
    const uint32_t kaCur = smb + KA_S + (uint32_t)((t & 1) << 14);
    const uint32_t vhCur = smb + VH_S + (uint32_t)((t & 1) << 15);
    const uint32_t gOff  = (uint32_t)(GIDX + ((t & 1) << 7));
    const uint32_t rkOff = (uint32_t)(RKS + ((t & 1) << 8));

    // prefetch t+1: ka, vh, gidx, rk
    if (t + 1 < ntiles) {
      issue16k(smb + KA_S + (uint32_t)(((t + 1) & 1) << 14),
               g_ka + ((size_t)(b * NTILES + t + 1) << 14), tid);
      issue32k(smb + VH_S + (uint32_t)(((t + 1) & 1) << 15),
               g_vh + ((size_t)(b * NTILES + t + 1) << 15), tid);
      if (tid < 8)
        cpa16(smb + GIDX + (uint32_t)(((t + 1) & 1) << 7) + tid * 16,
              (const unsigned char*)g_kidx + (size_t)b * L_ * 2 + (size_t)(t + 1) * 128 + tid * 16);
      if (tid < 16)
        cpa16(smb + RKS + (uint32_t)(((t + 1) & 1) << 8) + tid * 16,
              (const unsigned char*)g_rk + (size_t)b * L_ * 4 + (size_t)(t + 1) * 256 + tid * 16);
      CP_COMMIT();
    }

    // ---- QK int8: 3 passes (aa, ab+ba, bb), exact s32 accumulation ----
    float s[8][4];
    int acc[8][4];

    // pass 1: a*a (weight 65536)
    #pragma unroll
    for (int n = 0; n < 8; n++)
      #pragma unroll
      for (int c = 0; c < 4; c++) acc[n][c] = 0;
    #pragma unroll
    for (int ch = 0; ch < 8; ch++) {
      uint32_t af[4];
      ldsm4(af, smb + QA_S + swI(rowQ, 2 * ch + chA));
      #pragma unroll
      for (int j = 0; j < 4; j++) {
        uint32_t bf[4];
        ldsm4(bf, kaCur + swI(16 * j + keyB, 2 * ch + chB));
        mmai8(acc[2*j],   af, bf[0], bf[1]);
        mmai8(acc[2*j+1], af, bf[2], bf[3]);
      }
    }
    #pragma unroll
    for (int n = 0; n < 8; n++)
      #pragma unroll
      for (int c = 0; c < 4; c++) s[n][c] = (float)acc[n][c] * 65536.f;

    // pass 2: a*b + b*a (weight 256)
    #pragma unroll
    for (int n = 0; n < 8; n++)
      #pragma unroll
      for (int c = 0; c < 4; c++) acc[n][c] = 0;
    #pragma unroll
    for (int ch = 0; ch < 8; ch++) {
      uint32_t afA[4], afB[4];
      ldsm4(afA, smb + QA_S + swI(rowQ, 2 * ch + chA));
      ldsm4(afB, smb + QB_S + swI(rowQ, 2 * ch + chA));
      #pragma unroll
      for (int j = 0; j < 4; j++) {
        uint32_t bfA[4], bfB[4];
        ldsm4(bfA, kaCur + swI(16 * j + keyB, 2 * ch + chB));
        ldsm4(bfB, smb + KB_S + swI(16 * j + keyB, 2 * ch + chB));
        mmai8(acc[2*j],   afA, bfB[0], bfB[1]);
        mmai8(acc[2*j+1], afA, bfB[2], bfB[3]);
        mmai8(acc[2*j],   afB, bfA[0], bfA[1]);
        mmai8(acc[2*j+1], afB, bfA[2], bfA[3]);
      }
    }
    #pragma unroll
    for (int n = 0; n < 8; n++)
      #pragma unroll
      for (int c = 0; c < 4; c++) s[n][c] = fmaf((float)acc[n][c], 256.f, s[n][c]);

    // pass 3: b*b (weight 1)
    #pragma unroll
    for (int n = 0; n < 8; n++)
      #pragma unroll
      for (int c = 0; c < 4; c++) acc[n][c] = 0;
    #pragma unroll
    for (int ch = 0; ch < 8; ch++) {
      uint32_t af[4];
      ldsm4(af, smb + QB_S + swI(rowQ, 2 * ch + chA));
      #pragma unroll
      for (int j = 0; j < 4; j++) {
        uint32_t bf[4];
        ldsm4(bf, smb + KB_S + swI(16 * j + keyB, 2 * ch + chB));
        mmai8(acc[2*j],   af, bf[0], bf[1]);
        mmai8(acc[2*j+1], af, bf[2], bf[3]);
      }
    }

    // combine with per-row x per-slot scales: s = U * rq * rk
    #pragma unroll
    for (int nt = 0; nt < 8; nt++) {
      const int col0 = 8 * nt + 2 * t4;
      const float2 rk = *reinterpret_cast<const float2*>(sm + rkOff + col0 * 4);
      float u0 = (float)acc[nt][0] + s[nt][0];
      float u1 = (float)acc[nt][1] + s[nt][1];
      float u2 = (float)acc[nt][2] + s[nt][2];
      float u3 = (float)acc[nt][3] + s[nt][3];
      s[nt][0] = u0 * (rq0 * rk.x);
      s[nt][1] = u1 * (rq0 * rk.y);
      s[nt][2] = u2 * (rq1 * rk.x);
      s[nt][3] = u3 * (rq1 * rk.y);
    }

    __syncthreads();   // KB consumed by all warps

    if (t + 1 < ntiles) {
      issue16k(smb + KB_S, g_kb + ((size_t)(b * NTILES + t + 1) << 14), tid);
      CP_COMMIT();
    }

    // ---- softmax pass 1: diag zero + padding mask, row maxes ----
    float lm0 = -INFINITY, lm1 = -INFINITY;
    #pragma unroll
    for (int nt = 0; nt < 8; nt++) {
      const int col0 = 8 * nt + 2 * t4;
      const uint32_t gw = *reinterpret_cast<const uint32_t*>(sm + gOff + col0 * 2);
      const int gi0 = (int)(short)(gw & 0xFFFFu);
      const int gi1 = (int)(short)(gw >> 16);

      float v0 = (gi0 == qa) ? 0.f : s[nt][0];
      float v1 = (gi1 == qa) ? 0.f : s[nt][1];
      float v2 = (gi0 == qb) ? 0.f : s[nt][2];
      float v3 = (gi1 == qb) ? 0.f : s[nt][3];
      if (gi0 < 0) { v0 = -INFINITY; v2 = -INFINITY; }
      if (gi1 < 0) { v1 = -INFINITY; v3 = -INFINITY; }
      s[nt][0] = v0; s[nt][1] = v1; s[nt][2] = v2; s[nt][3] = v3;
      lm0 = fmaxf(lm0, fmaxf(v0, v1));
      lm1 = fmaxf(lm1, fmaxf(v2, v3));
    }
    lm0 = fmaxf(lm0, __shfl_xor_sync(0xffffffffu, lm0, 1));
    lm0 = fmaxf(lm0, __shfl_xor_sync(0xffffffffu, lm0, 2));
    lm1 = fmaxf(lm1, __shfl_xor_sync(0xffffffffu, lm1, 1));
    lm1 = fmaxf(lm1, __shfl_xor_sync(0xffffffffu, lm1, 2));

    // ---- lazy offset raise (keep p within fp16 range) ----
    const bool r0 = lm0 > off0 + 10.f;
    const bool r1 = lm1 > off1 + 10.f;
    if (r0 || r1) {
      const float no0 = r0 ? (lm0 - 6.f) : off0;
      const float no1 = r1 ? (lm1 - 6.f) : off1;
      const float a0 = ex2f((off0 - no0) * L2E);
      const float a1 = ex2f((off1 - no1) * L2E);
      off0 = no0; off1 = no1;
      c0 = off0 * L2E; c1 = off1 * L2E;
      rs0 *= a0; rs1 *= a1;
      #pragma unroll
      for (int n = 0; n < 32; n++) {
        o[n][0] *= a0; o[n][1] *= a0;
        o[n][2] *= a1; o[n][3] *= a1;
      }
    }

    // ---- softmax pass 2: exp (MUFU), row sums, pack P fp16 ----
    uint32_t phi[4][4];
    #pragma unroll
    for (int nt = 0; nt < 8; nt++) {
      float p0 = ex2f(fmaf(s[nt][0], L2E, -c0));
      float p1 = ex2f(fmaf(s[nt][1], L2E, -c0));
      float p2 = ex2f(fmaf(s[nt][2], L2E, -c1));
      float p3 = ex2f(fmaf(s[nt][3], L2E, -c1));
      rs0 += p0 + p1;
      rs1 += p2 + p3;
      const int kc = nt >> 1;
      if ((nt & 1) == 0) {
        phi[kc][0] = packh2(p0, p1);
        phi[kc][1] = packh2(p2, p3);
      } else {
        phi[kc][2] = packh2(p0, p1);
        phi[kc][3] = packh2(p2, p3);
      }
    }

    // ---- O += P V (fp16, 1 term) ----
    #pragma unroll
    for (int kc = 0; kc < 4; kc++) {
      #pragma unroll
      for (int np = 0; np < 8; np++) {
        uint32_t vh0[4], vh1[4];
        const int dcol = 32 * np + dVoff;
        ldsm4t(vh0, vhCur + swH(16 * kc + keyV, dcol));
        ldsm4t(vh1, vhCur + swH(16 * kc + keyV, dcol + 16));
        mmaf16(o[4*np+0], phi[kc], vh0[0], vh0[1]);
        mmaf16(o[4*np+1], phi[kc], vh0[2], vh0[3]);
        mmaf16(o[4*np+2], phi[kc], vh1[0], vh1[1]);
        mmaf16(o[4*np+3], phi[kc], vh1[2], vh1[3]);
      }
    }

    CP_WAIT0();
    __syncthreads();
  }

  // ---- epilogue ----
  rs0 += __shfl_xor_sync(0xffffffffu, rs0, 1);
  rs0 += __shfl_xor_sync(0xffffffffu, rs0, 2);
  rs1 += __shfl_xor_sync(0xffffffffu, rs1, 1);
  rs1 += __shfl_xor_sync(0xffffffffu, rs1, 2);
  const float inv0 = (rs0 > 0.f) ? (1.f / rs0) : 0.f;
  const float inv1 = (rs1 > 0.f) ? (1.f / rs1) : 0.f;

  float* outa = out + ((size_t)b * L_ + qa) * D_;
  float* outb = out + ((size_t)b * L_ + qb) * D_;
  #pragma unroll
  for (int nt = 0; nt < 32; nt++) {
    const int dcol = 8 * nt + 2 * t4;
    float2 va; va.x = o[nt][0] * inv0; va.y = o[nt][1] * inv0;
    float2 vb; vb.x = o[nt][2] * inv1; vb.y = o[nt][3] * inv1;
    *reinterpret_cast<float2*>(outa + dcol) = va;
    *reinterpret_cast<float2*>(outb + dcol) = vb;
  }
}

} // namespace

extern "C" void kernel_launch(void* const* d_in, const int* in_sizes, int n_in,
                              void* d_out, int out_size)
{
  const float* x     = (const float*)d_in[0];
  const void*  xmask = d_in[1];
  float*       out   = (float*)d_out;

  amax_kernel<<<(B_ * L_ * 32) / 256, 256>>>(x);
  scan_mask_kernel<<<B_, 256>>>(xmask);
  prep_kernel<<<(B_ * L_ * 16) / 256, 256>>>(x);
  pad_k_kernel<<<(B_ * 64 * 16) / 256, 256>>>();

  cudaFuncSetAttribute(attn_kernel, cudaFuncAttributeMaxDynamicSharedMemorySize, SMEM_TOTAL);
  dim3 grid(L_ / BM, B_);
  attn_kernel<<<grid, NT, SMEM_TOTAL>>>(out);
}